// round 11
// baseline (speedup 1.0000x reference)
#include <cuda_runtime.h>
#include <math_constants.h>

// feature_matrix_batch: [S=2, N=32, I=4096, D=128] f32
// cluster_index:        [S, N*I] int32 or int64, values in [n*K,(n+1)*K)
// output:               [S, N, K=16, D=128] f32 segment max (-inf identity)

#define SS      2
#define NN      32
#define II      4096
#define DD      128
#define KK      16
#define CHUNKS  16
#define PTS     (II / CHUNKS)        // 256 points per block
#define NBLK    (SS * NN * CHUNKS)   // 1024 blocks
#define ROWF4   32                   // float4 per row (128 floats)
#define TILE    (KK * ROWF4)         // 512 float4 per block partial

// Per-block partials: [1024][512 f4] = 8 MB, plus per-cloud arrival counters.
__device__ float4 g_scratch4[NBLK * TILE];
__device__ int    g_count[SS * NN];   // zero-init; reset by reducer each run

static __device__ __forceinline__ float4 vmax4(float4 a, float4 b) {
    a.x = fmaxf(a.x, b.x);
    a.y = fmaxf(a.y, b.y);
    a.z = fmaxf(a.z, b.z);
    a.w = fmaxf(a.w, b.w);
    return a;
}

__global__ void __launch_bounds__(128) maxpool_fused(
    const float4* __restrict__ f4,
    const int*    __restrict__ cw,     // raw 32-bit view of cluster_index
    float4*       __restrict__ out4)
{
    const int b     = blockIdx.x;
    const int chunk = b & (CHUNKS - 1);
    const int cloud = b >> 4;                 // CHUNKS == 16
    const int n     = cloud & (NN - 1);
    const int x     = threadIdx.x;
    const int w     = x >> 5;
    const int lane  = x & 31;

    __shared__ unsigned short plist[PTS];     // points sorted by segment
    __shared__ unsigned char  skk[PTS];       // per-point clamped segment id
    __shared__ int hist[KK + 1];              // counts (bucket 16 = invalid)
    __shared__ int cstart[KK + 1];            // exclusive prefix
    __shared__ int cursor[KK + 1];            // scatter cursors
    __shared__ int s_last;

    // dtype sniff: indices < 512 -> int64 high (odd) words all zero.
    const bool is64 =
        ((cw[1] | cw[3] | cw[5] | cw[7] | cw[9] | cw[11] | cw[13] | cw[15]) == 0);

    if (x <= KK) hist[x] = 0;
    __syncthreads();

    // ---- stage indices + histogram (2 points per thread) ----
    const size_t idx_base = (size_t)cloud * II + (size_t)chunk * PTS;
    #pragma unroll
    for (int j = x; j < PTS; j += 128) {
        int k = (is64 ? cw[2 * (idx_base + j)] : cw[idx_base + j]) - n * KK;
        k = (int)min((unsigned)k, (unsigned)KK);
        skk[j] = (unsigned char)k;
        atomicAdd(&hist[k], 1);
    }
    __syncthreads();

    if (x == 0) {
        int acc = 0;
        #pragma unroll
        for (int k = 0; k <= KK; k++) {
            cstart[k] = acc;
            cursor[k] = acc;
            acc += hist[k];
        }
    }
    __syncthreads();

    // ---- scatter point ids into segment-ordered list ----
    #pragma unroll
    for (int j = x; j < PTS; j += 128) {
        int p = atomicAdd(&cursor[skk[j]], 1);
        plist[p] = (unsigned short)j;
    }
    __syncthreads();

    // ---- register-accumulator gather reduction ----
    // Warp w owns segments [4w, 4w+4). Lane l owns feature cols [4l, 4l+4).
    const float4 neg4 = make_float4(-CUDART_INF_F, -CUDART_INF_F,
                                    -CUDART_INF_F, -CUDART_INF_F);
    const float4* fbase = f4 + ((size_t)cloud * II + (size_t)chunk * PTS) * ROWF4
                             + lane;
    float4* dst = g_scratch4 + (size_t)b * TILE;

    #pragma unroll
    for (int si = 0; si < 4; si++) {
        const int s   = w * 4 + si;
        const int st  = cstart[s];
        const int cnt = hist[s];

        float4 a0 = neg4, a1 = neg4, a2 = neg4, a3 = neg4;
        int i = 0;
        for (; i + 4 <= cnt; i += 4) {
            const int p0 = plist[st + i + 0];      // broadcast LDS
            const int p1 = plist[st + i + 1];
            const int p2 = plist[st + i + 2];
            const int p3 = plist[st + i + 3];
            const float4 v0 = fbase[p0 * ROWF4];   // 4 independent LDG.128
            const float4 v1 = fbase[p1 * ROWF4];
            const float4 v2 = fbase[p2 * ROWF4];
            const float4 v3 = fbase[p3 * ROWF4];
            a0 = vmax4(a0, v0);
            a1 = vmax4(a1, v1);
            a2 = vmax4(a2, v2);
            a3 = vmax4(a3, v3);
        }
        for (; i < cnt; i++) {
            const int p = plist[st + i];
            a0 = vmax4(a0, fbase[p * ROWF4]);
        }
        const float4 a = vmax4(vmax4(a0, a1), vmax4(a2, a3));
        dst[s * ROWF4 + lane] = a;                 // exclusive: no merge needed
    }

    // ---- last block of each cloud reduces its 16 partials to out ----
    __threadfence();
    __syncthreads();
    if (x == 0)
        s_last = (atomicAdd(&g_count[cloud], 1) == CHUNKS - 1);
    __syncthreads();

    if (s_last) {
        __threadfence();   // acquire-side: order partial reads after counter
        const float4* base = g_scratch4 + (size_t)cloud * CHUNKS * TILE;
        float4*       dout = out4 + (size_t)cloud * TILE;
        #pragma unroll
        for (int q = 0; q < 4; q++) {
            const int idx = x + 128 * q;
            float4 m = base[idx];
            #pragma unroll
            for (int c = 1; c < CHUNKS; c++)
                m = vmax4(m, base[(size_t)c * TILE + idx]);
            dout[idx] = m;
        }
        if (x == 0) g_count[cloud] = 0;   // rearm for next graph replay
    }
}

extern "C" void kernel_launch(void* const* d_in, const int* in_sizes, int n_in,
                              void* d_out, int out_size)
{
    const float4* f4  = (const float4*)d_in[0];
    const int*    cw  = (const int*)d_in[1];
    float4*       out = (float4*)d_out;

    maxpool_fused<<<NBLK, 128>>>(f4, cw, out);
}

// round 12
// speedup vs baseline: 1.0747x; 1.0747x over previous
#include <cuda_runtime.h>
#include <math_constants.h>

// feature_matrix_batch: [S=2, N=32, I=4096, D=128] f32
// cluster_index:        [S, N*I] int32 or int64, values in [n*K,(n+1)*K)
// output:               [S, N, K=16, D=128] f32 segment max (-inf identity)

#define SS      2
#define NN      32
#define II      4096
#define DD      128
#define KK      16
#define CHUNKS  8
#define PTS     (II / CHUNKS)        // 512 points per block
#define NBLK    (SS * NN * CHUNKS)   // 512 blocks
#define ROWF4   32                   // float4 per row
#define ROWF2   64                   // float2 per row
#define TILE    (KK * ROWF4)         // 512 float4 per block partial
#define PAIRS   4                    // warp pairs per block (8 warps)
#define PPTS    (PTS / PAIRS)        // 128 points per pair
#define GRP     4
#define NGRP    (PPTS / GRP)         // 32 groups
#define DEPTH   2

// Per-block partials: [512][512 f4] = 4 MB, plus per-cloud arrival counters.
__device__ float4 g_scratch4[NBLK * TILE];
__device__ int    g_count[SS * NN];   // zero-init; reset by reducer each run

static __device__ __forceinline__ float4 vmax4(float4 a, float4 b) {
    a.x = fmaxf(a.x, b.x);
    a.y = fmaxf(a.y, b.y);
    a.z = fmaxf(a.z, b.z);
    a.w = fmaxf(a.w, b.w);
    return a;
}

__global__ void __launch_bounds__(256) maxpool_fused(
    const float4* __restrict__ f4,
    const int*    __restrict__ cw,     // raw 32-bit view of cluster_index
    float4*       __restrict__ out4)
{
    const int b     = blockIdx.x;
    const int chunk = b & (CHUNKS - 1);
    const int cloud = b >> 3;                 // CHUNKS == 8
    const int n     = cloud & (NN - 1);
    const int x     = threadIdx.x;
    const int w     = x >> 5;
    const int lane  = x & 31;
    const int pair  = w >> 1;                 // 0..3
    const int half  = w & 1;                  // column half within the pair

    // Pair-shared tiles; warp A touches float2 cols [0,32), warp B [32,64):
    // disjoint addresses -> race-free without atomics. Row 16 = trash row.
    __shared__ float2 smaxw[PAIRS][KK + 1][ROWF2];  // ~34.8 KB
    __shared__ int    soff[PTS];                    // 2 KB
    __shared__ int    s_last;

    // dtype sniff: indices < 512 -> int64 high (odd) words all zero.
    const bool is64 =
        ((cw[1] | cw[3] | cw[5] | cw[7] | cw[9] | cw[11] | cw[13] | cw[15]) == 0);

    const int pos = half * 32 + lane;         // this warp's float2 column
    const float2 neg2 = make_float2(-CUDART_INF_F, -CUDART_INF_F);
    #pragma unroll
    for (int r = 0; r <= KK; r++)
        smaxw[pair][r][pos] = neg2;

    // Stage indices -> clamped local segment id (branch-free consumer).
    const size_t idx_base = (size_t)cloud * II + (size_t)chunk * PTS;
    if (is64) {
        #pragma unroll
        for (int j = x; j < PTS; j += 256) {
            int k = cw[2 * (idx_base + j)] - n * KK;   // low word of int64
            soff[j] = (int)min((unsigned)k, (unsigned)KK);
        }
    } else {
        #pragma unroll
        for (int j = x; j < PTS; j += 256) {
            int k = cw[idx_base + j] - n * KK;
            soff[j] = (int)min((unsigned)k, (unsigned)KK);
        }
    }
    __syncthreads();

    // Pair p owns contiguous points [p*128, (p+1)*128); both warps of the
    // pair walk the same points, each loading its 256B half-row (LDG.64).
    const int     pbase = pair * PPTS;
    const float2* fp = (const float2*)f4
                     + ((size_t)cloud * II + (size_t)chunk * PTS + pbase) * ROWF2
                     + pos;
    float2* const my = &smaxw[pair][0][pos];   // row stride = ROWF2 float2

    // ---- depth-2 pipeline: 8 LDG.64 (2 KB) in flight per warp ----
    float2 vb[DEPTH][GRP];
    int    kb[DEPTH][GRP];
    #pragma unroll
    for (int d = 0; d < DEPTH; d++)
        #pragma unroll
        for (int u = 0; u < GRP; u++) {
            vb[d][u] = fp[(d * GRP + u) * ROWF2];
            kb[d][u] = soff[pbase + d * GRP + u];
        }

    #pragma unroll
    for (int g = 0; g < NGRP; g++) {
        const int s = g & (DEPTH - 1);
        #pragma unroll
        for (int u = 0; u < GRP; u++) {        // consume group g
            const int    k = kb[s][u];
            const float2 v = vb[s][u];
            float2 c = my[k * ROWF2];
            c.x = fmaxf(c.x, v.x);
            c.y = fmaxf(c.y, v.y);
            my[k * ROWF2] = c;
        }
        if (g + DEPTH < NGRP) {                // refill with group g+DEPTH
            #pragma unroll
            for (int u = 0; u < GRP; u++) {
                vb[s][u] = fp[((g + DEPTH) * GRP + u) * ROWF2];
                kb[s][u] = soff[pbase + (g + DEPTH) * GRP + u];
            }
        }
    }
    __syncthreads();

    // ---- merge the 4 pair-copies, write block partial (float2 lanes) ----
    float2* dst2 = (float2*)(g_scratch4 + (size_t)b * TILE);  // [16][64] f2
    #pragma unroll
    for (int q = 0; q < 4; q++) {
        const int idx = x + 256 * q;           // 0..1023
        const int r = idx >> 6, l = idx & 63;
        float2 a  = smaxw[0][r][l];
        const float2 b1 = smaxw[1][r][l];
        const float2 b2 = smaxw[2][r][l];
        const float2 b3 = smaxw[3][r][l];
        a.x = fmaxf(fmaxf(a.x, b1.x), fmaxf(b2.x, b3.x));
        a.y = fmaxf(fmaxf(a.y, b1.y), fmaxf(b2.y, b3.y));
        dst2[idx] = a;
    }

    // ---- last block of each cloud reduces its 8 partials to out ----
    __threadfence();
    __syncthreads();
    if (x == 0)
        s_last = (atomicAdd(&g_count[cloud], 1) == CHUNKS - 1);
    __syncthreads();

    if (s_last) {
        __threadfence();   // acquire-side: order partial reads after counter
        const float4* base = g_scratch4 + (size_t)cloud * CHUNKS * TILE;
        float4*       dout = out4 + (size_t)cloud * TILE;
        #pragma unroll
        for (int q = 0; q < 2; q++) {
            const int idx = x + 256 * q;       // 0..511 float4
            float4 m = base[idx];
            #pragma unroll
            for (int c = 1; c < CHUNKS; c++)
                m = vmax4(m, base[(size_t)c * TILE + idx]);
            dout[idx] = m;
        }
        if (x == 0) g_count[cloud] = 0;   // rearm for next graph replay
    }
}

extern "C" void kernel_launch(void* const* d_in, const int* in_sizes, int n_in,
                              void* d_out, int out_size)
{
    const float4* f4  = (const float4*)d_in[0];
    const int*    cw  = (const int*)d_in[1];
    float4*       out = (float4*)d_out;

    maxpool_fused<<<NBLK, 256>>>(f4, cw, out);
}

// round 13
// speedup vs baseline: 1.3161x; 1.2246x over previous
#include <cuda_runtime.h>
#include <math_constants.h>
#include <cstdint>

// feature_matrix_batch: [S=2, N=32, I=4096, D=128] f32
// cluster_index:        [S, N*I] int32 or int64, values in [n*K,(n+1)*K)
// output:               [S, N, K=16, D=128] f32 segment max (-inf identity)

#define SS       2
#define NN       32
#define II       4096
#define DD       128
#define KK       16
#define CHUNKS   4
#define PTS      (II / CHUNKS)         // 1024 points per block
#define NBLK     (SS * NN * CHUNKS)    // 256 blocks
#define ROWF4    32                    // float4 per point-row
#define TILE     (KK * ROWF4)          // 512 float4 per block partial

#define STAGES      4
#define SPTS        32                          // points per stage
#define STAGE_BYTES (SPTS * DD * 4)             // 16 KB
#define NSTEP       (PTS / SPTS)                // 32 stages per block
#define NTHREADS    288                         // 8 consumer warps + 1 producer

// smem layout (dynamic): buffers | kloc | mbarriers
#define SM_BUF   0
#define SM_KLOC  (STAGES * STAGE_BYTES)         // 65536
#define SM_BAR   (SM_KLOC + PTS)                // 66560 (8B aligned)
#define SM_TOTAL (SM_BAR + 16 * 8)              // 66688

// Per-block partials: [256][512 f4] = 2 MB, plus per-cloud arrival counters.
__device__ float4 g_scratch4[NBLK * TILE];
__device__ int    g_count[SS * NN];   // zero-init; reset by reducer each run

static __device__ __forceinline__ float4 vmax4(float4 a, float4 b) {
    a.x = fmaxf(a.x, b.x);
    a.y = fmaxf(a.y, b.y);
    a.z = fmaxf(a.z, b.z);
    a.w = fmaxf(a.w, b.w);
    return a;
}

static __device__ __forceinline__ uint32_t smem_u32(const void* p) {
    return (uint32_t)__cvta_generic_to_shared(p);
}

#define MBAR_INIT(addr, cnt) \
    asm volatile("mbarrier.init.shared.b64 [%0], %1;" :: "r"(addr), "r"(cnt) : "memory")
#define MBAR_EXPECT_TX(addr, tx) \
    asm volatile("mbarrier.arrive.expect_tx.shared.b64 _, [%0], %1;" :: "r"(addr), "r"(tx) : "memory")
#define MBAR_ARRIVE(addr) \
    asm volatile("mbarrier.arrive.shared.b64 _, [%0];" :: "r"(addr) : "memory")
#define MBAR_WAIT(addr, parity) do {                                          \
    asm volatile(                                                             \
        "{\n\t.reg .pred P1;\n\t"                                             \
        "WAIT_LOOP_%=:\n\t"                                                   \
        "mbarrier.try_wait.parity.acquire.cta.shared::cta.b64 P1, [%0], %1;\n\t" \
        "@P1 bra.uni WAIT_DONE_%=;\n\t"                                       \
        "bra.uni WAIT_LOOP_%=;\n\t"                                           \
        "WAIT_DONE_%=:\n\t}"                                                  \
        :: "r"(addr), "r"(parity) : "memory");                                \
} while (0)
#define BULK_CP(dst, src, bytes, bar) \
    asm volatile("cp.async.bulk.shared::cluster.global.mbarrier::complete_tx::bytes " \
                 "[%0], [%1], %2, [%3];" \
                 :: "r"(dst), "l"(src), "r"(bytes), "r"(bar) : "memory")

__global__ void __launch_bounds__(NTHREADS) maxpool_fused(
    const float4* __restrict__ f4,
    const int*    __restrict__ cw,     // raw 32-bit view of cluster_index
    float4*       __restrict__ out4)
{
    extern __shared__ __align__(1024) char smem[];
    float*         buf  = (float*)(smem + SM_BUF);
    unsigned char* kloc = (unsigned char*)(smem + SM_KLOC);
    const uint32_t bar0 = smem_u32(smem + SM_BAR);
    // full[s] = bar0 + 8*s ; empty[s] = bar0 + 8*(STAGES+s)

    const int b     = blockIdx.x;
    const int chunk = b & (CHUNKS - 1);
    const int cloud = b >> 2;                 // CHUNKS == 4
    const int n     = cloud & (NN - 1);
    const int x     = threadIdx.x;
    const int w     = x >> 5;
    const int lane  = x & 31;

    __shared__ int s_last;

    if (x == 0) {
        #pragma unroll
        for (int s = 0; s < STAGES; s++) {
            MBAR_INIT(bar0 + 8 * s, 1);                  // full: producer arrive
            MBAR_INIT(bar0 + 8 * (STAGES + s), 8);       // empty: 8 consumer warps
        }
    }

    // dtype sniff: indices < 512 -> int64 high (odd) words all zero.
    const bool is64 =
        ((cw[1] | cw[3] | cw[5] | cw[7] | cw[9] | cw[11] | cw[13] | cw[15]) == 0);

    // Stage indices -> clamped local segment id (16 = unowned trash).
    const size_t idx_base = (size_t)cloud * II + (size_t)chunk * PTS;
    if (is64) {
        for (int j = x; j < PTS; j += NTHREADS) {
            int k = cw[2 * (idx_base + j)] - n * KK;     // low word of int64
            kloc[j] = (unsigned char)min((unsigned)k, (unsigned)KK);
        }
    } else {
        for (int j = x; j < PTS; j += NTHREADS) {
            int k = cw[idx_base + j] - n * KK;
            kloc[j] = (unsigned char)min((unsigned)k, (unsigned)KK);
        }
    }
    __syncthreads();

    const char* gsrc = (const char*)(f4 + ((size_t)cloud * II + (size_t)chunk * PTS) * ROWF4);

    if (w == 8) {
        // ---------------- producer: one elected thread ----------------
        if (lane == 0) {
            for (int g = 0; g < NSTEP; g++) {
                const int s  = g & (STAGES - 1);
                const int pe = 1 ^ ((g >> 2) & 1);       // wrap parity (init 1)
                MBAR_WAIT(bar0 + 8 * (STAGES + s), pe);
                MBAR_EXPECT_TX(bar0 + 8 * s, STAGE_BYTES);
                BULK_CP(smem_u32(buf) + s * STAGE_BYTES,
                        (const void*)(gsrc + (size_t)g * STAGE_BYTES),
                        STAGE_BYTES, bar0 + 8 * s);
            }
        }
    } else {
        // ---------------- consumers: warp w owns segments 2w, 2w+1 ----
        const float4 neg4 = make_float4(-CUDART_INF_F, -CUDART_INF_F,
                                        -CUDART_INF_F, -CUDART_INF_F);
        float4 acc0 = neg4, acc1 = neg4;

        for (int g = 0; g < NSTEP; g++) {
            const int s  = g & (STAGES - 1);
            const int pf = (g >> 2) & 1;
            MBAR_WAIT(bar0 + 8 * s, pf);

            const int ki_lane = kloc[g * SPTS + lane];   // 1 point per lane
            unsigned m = __ballot_sync(0xffffffffu, (ki_lane >> 1) == w);

            const float4* rows = (const float4*)(buf + (size_t)s * (SPTS * DD));
            while (m) {
                const int i = __ffs(m) - 1;
                m &= m - 1;
                const int    ki = __shfl_sync(0xffffffffu, ki_lane, i);
                const float4 v  = rows[i * ROWF4 + lane];  // LDS.128
                if (ki & 1) acc1 = vmax4(acc1, v);
                else        acc0 = vmax4(acc0, v);
            }
            __syncwarp();
            if (lane == 0) MBAR_ARRIVE(bar0 + 8 * (STAGES + s));
        }

        // exclusive writes: no merge needed
        float4* dst = g_scratch4 + (size_t)b * TILE;
        dst[(2 * w + 0) * ROWF4 + lane] = acc0;
        dst[(2 * w + 1) * ROWF4 + lane] = acc1;
    }

    // ---- last block of each cloud reduces its 4 partials to out ----
    __threadfence();
    __syncthreads();
    if (x == 0)
        s_last = (atomicAdd(&g_count[cloud], 1) == CHUNKS - 1);
    __syncthreads();

    if (s_last) {
        __threadfence();   // acquire-side: order partial reads after counter
        const float4* base = g_scratch4 + (size_t)cloud * CHUNKS * TILE;
        float4*       dout = out4 + (size_t)cloud * TILE;
        for (int idx = x; idx < TILE; idx += NTHREADS) {
            float4 mv = base[idx];
            #pragma unroll
            for (int c = 1; c < CHUNKS; c++)
                mv = vmax4(mv, base[(size_t)c * TILE + idx]);
            dout[idx] = mv;
        }
        if (x == 0) g_count[cloud] = 0;   // rearm for next graph replay
    }
}

extern "C" void kernel_launch(void* const* d_in, const int* in_sizes, int n_in,
                              void* d_out, int out_size)
{
    const float4* f4  = (const float4*)d_in[0];
    const int*    cw  = (const int*)d_in[1];
    float4*       out = (float4*)d_out;

    // Set once on the (uncaptured) correctness call; persists for capture.
    static bool attr_done = false;
    if (!attr_done) {
        cudaFuncSetAttribute(maxpool_fused,
                             cudaFuncAttributeMaxDynamicSharedMemorySize, SM_TOTAL);
        attr_done = true;
    }
    maxpool_fused<<<NBLK, NTHREADS, SM_TOTAL>>>(f4, cw, out);
}

// round 14
// speedup vs baseline: 1.3268x; 1.0082x over previous
#include <cuda_runtime.h>
#include <math_constants.h>
#include <cstdint>

// feature_matrix_batch: [S=2, N=32, I=4096, D=128] f32
// cluster_index:        [S, N*I] int32 or int64, values in [n*K,(n+1)*K)
// output:               [S, N, K=16, D=128] f32 segment max (-inf identity)

#define SS       2
#define NN       32
#define II       4096
#define DD       128
#define KK       16
#define CHUNKS   4
#define PTS      (II / CHUNKS)         // 1024 points per block
#define NBLK     (SS * NN * CHUNKS)    // 256 blocks
#define ROWF4    32                    // float4 per point-row
#define TILE     (KK * ROWF4)          // 512 float4 per block partial

#define STAGES      4
#define SPTS        32                          // points per stage
#define STAGE_BYTES (SPTS * DD * 4)             // 16 KB
#define NSTEP       (PTS / SPTS)                // 32 stages per block
#define NTHREADS    288                         // 8 consumer warps + 1 producer

// smem layout (dynamic): buffers | kloc | mbarriers
#define SM_BUF   0
#define SM_KLOC  (STAGES * STAGE_BYTES)         // 65536
#define SM_BAR   (SM_KLOC + PTS)                // 66560 (8B aligned)
#define SM_TOTAL (SM_BAR + 16 * 8)              // 66688

// Per-block partials: [256][512 f4] = 2 MB, plus per-cloud arrival counters.
__device__ float4 g_scratch4[NBLK * TILE];
__device__ int    g_count[SS * NN];   // zero-init; reset by reducer each run

static __device__ __forceinline__ float4 vmax4(float4 a, float4 b) {
    a.x = fmaxf(a.x, b.x);
    a.y = fmaxf(a.y, b.y);
    a.z = fmaxf(a.z, b.z);
    a.w = fmaxf(a.w, b.w);
    return a;
}

static __device__ __forceinline__ uint32_t smem_u32(const void* p) {
    return (uint32_t)__cvta_generic_to_shared(p);
}

#define MBAR_INIT(addr, cnt) \
    asm volatile("mbarrier.init.shared.b64 [%0], %1;" :: "r"(addr), "r"(cnt) : "memory")
#define MBAR_EXPECT_TX(addr, tx) \
    asm volatile("mbarrier.arrive.expect_tx.shared.b64 _, [%0], %1;" :: "r"(addr), "r"(tx) : "memory")
#define MBAR_ARRIVE(addr) \
    asm volatile("mbarrier.arrive.shared.b64 _, [%0];" :: "r"(addr) : "memory")
#define MBAR_WAIT(addr, parity) do {                                          \
    asm volatile(                                                             \
        "{\n\t.reg .pred P1;\n\t"                                             \
        "WAIT_LOOP_%=:\n\t"                                                   \
        "mbarrier.try_wait.parity.acquire.cta.shared::cta.b64 P1, [%0], %1;\n\t" \
        "@P1 bra.uni WAIT_DONE_%=;\n\t"                                       \
        "bra.uni WAIT_LOOP_%=;\n\t"                                           \
        "WAIT_DONE_%=:\n\t}"                                                  \
        :: "r"(addr), "r"(parity) : "memory");                                \
} while (0)
#define BULK_CP(dst, src, bytes, bar) \
    asm volatile("cp.async.bulk.shared::cluster.global.mbarrier::complete_tx::bytes " \
                 "[%0], [%1], %2, [%3];" \
                 :: "r"(dst), "l"(src), "r"(bytes), "r"(bar) : "memory")

__global__ void __launch_bounds__(NTHREADS) maxpool_fused(
    const float4* __restrict__ f4,
    const int*    __restrict__ cw,     // raw 32-bit view of cluster_index
    float4*       __restrict__ out4)
{
    extern __shared__ __align__(1024) char smem[];
    float*         buf  = (float*)(smem + SM_BUF);
    unsigned char* kloc = (unsigned char*)(smem + SM_KLOC);
    const uint32_t bar0 = smem_u32(smem + SM_BAR);
    // full[s] = bar0 + 8*s ; empty[s] = bar0 + 8*(STAGES+s)

    const int b     = blockIdx.x;
    const int chunk = b & (CHUNKS - 1);
    const int cloud = b >> 2;                 // CHUNKS == 4
    const int n     = cloud & (NN - 1);
    const int x     = threadIdx.x;
    const int w     = x >> 5;
    const int lane  = x & 31;

    __shared__ int s_last;

    if (x == 0) {
        #pragma unroll
        for (int s = 0; s < STAGES; s++) {
            MBAR_INIT(bar0 + 8 * s, 1);                  // full: producer arrive
            MBAR_INIT(bar0 + 8 * (STAGES + s), 8);       // empty: 8 consumer warps
        }
    }

    // dtype sniff: indices < 512 -> int64 high (odd) words all zero.
    const bool is64 =
        ((cw[1] | cw[3] | cw[5] | cw[7] | cw[9] | cw[11] | cw[13] | cw[15]) == 0);

    // Stage indices -> clamped local segment id (16 = unowned trash).
    const size_t idx_base = (size_t)cloud * II + (size_t)chunk * PTS;
    if (is64) {
        for (int j = x; j < PTS; j += NTHREADS) {
            int k = cw[2 * (idx_base + j)] - n * KK;     // low word of int64
            kloc[j] = (unsigned char)min((unsigned)k, (unsigned)KK);
        }
    } else {
        for (int j = x; j < PTS; j += NTHREADS) {
            int k = cw[idx_base + j] - n * KK;
            kloc[j] = (unsigned char)min((unsigned)k, (unsigned)KK);
        }
    }
    __syncthreads();

    const char* gsrc = (const char*)(f4 + ((size_t)cloud * II + (size_t)chunk * PTS) * ROWF4);

    if (w == 8) {
        // ---------------- producer: one elected thread ----------------
        if (lane == 0) {
            for (int g = 0; g < NSTEP; g++) {
                const int s  = g & (STAGES - 1);
                const int pe = 1 ^ ((g >> 2) & 1);       // wrap parity (init 1)
                MBAR_WAIT(bar0 + 8 * (STAGES + s), pe);
                MBAR_EXPECT_TX(bar0 + 8 * s, STAGE_BYTES);
                BULK_CP(smem_u32(buf) + s * STAGE_BYTES,
                        (const void*)(gsrc + (size_t)g * STAGE_BYTES),
                        STAGE_BYTES, bar0 + 8 * s);
            }
        }
    } else {
        // ---------------- consumers: warp w owns segments 2w, 2w+1 ----
        const float4 neg4 = make_float4(-CUDART_INF_F, -CUDART_INF_F,
                                        -CUDART_INF_F, -CUDART_INF_F);
        float4 acc0 = neg4, acc1 = neg4;

        for (int g = 0; g < NSTEP; g++) {
            const int s  = g & (STAGES - 1);
            const int pf = (g >> 2) & 1;
            MBAR_WAIT(bar0 + 8 * s, pf);

            const int ki_lane = kloc[g * SPTS + lane];   // 1 point per lane
            unsigned m = __ballot_sync(0xffffffffu, (ki_lane >> 1) == w);

            const float4* rows = (const float4*)(buf + (size_t)s * (SPTS * DD));
            while (m) {
                const int i = __ffs(m) - 1;
                m &= m - 1;
                const int    ki = __shfl_sync(0xffffffffu, ki_lane, i);
                const float4 v  = rows[i * ROWF4 + lane];  // LDS.128
                if (ki & 1) acc1 = vmax4(acc1, v);
                else        acc0 = vmax4(acc0, v);
            }
            __syncwarp();
            if (lane == 0) MBAR_ARRIVE(bar0 + 8 * (STAGES + s));
        }

        // exclusive writes: no merge needed
        float4* dst = g_scratch4 + (size_t)b * TILE;
        dst[(2 * w + 0) * ROWF4 + lane] = acc0;
        dst[(2 * w + 1) * ROWF4 + lane] = acc1;
    }

    // ---- last block of each cloud reduces its 4 partials to out ----
    __threadfence();
    __syncthreads();
    if (x == 0)
        s_last = (atomicAdd(&g_count[cloud], 1) == CHUNKS - 1);
    __syncthreads();

    if (s_last) {
        __threadfence();   // acquire-side: order partial reads after counter
        const float4* base = g_scratch4 + (size_t)cloud * CHUNKS * TILE;
        float4*       dout = out4 + (size_t)cloud * TILE;
        for (int idx = x; idx < TILE; idx += NTHREADS) {
            float4 mv = base[idx];
            #pragma unroll
            for (int c = 1; c < CHUNKS; c++)
                mv = vmax4(mv, base[(size_t)c * TILE + idx]);
            dout[idx] = mv;
        }
        if (x == 0) g_count[cloud] = 0;   // rearm for next graph replay
    }
}

extern "C" void kernel_launch(void* const* d_in, const int* in_sizes, int n_in,
                              void* d_out, int out_size)
{
    const float4* f4  = (const float4*)d_in[0];
    const int*    cw  = (const int*)d_in[1];
    float4*       out = (float4*)d_out;

    // Set once on the (uncaptured) correctness call; persists for capture.
    static bool attr_done = false;
    if (!attr_done) {
        cudaFuncSetAttribute(maxpool_fused,
                             cudaFuncAttributeMaxDynamicSharedMemorySize, SM_TOTAL);
        attr_done = true;
    }
    maxpool_fused<<<NBLK, NTHREADS, SM_TOTAL>>>(f4, cw, out);
}